// round 15
// baseline (speedup 1.0000x reference)
#include <cuda_runtime.h>

#define SQ 2048
#define BB 2
#define NH 12
#define DK 5
#define DM 64
#define DI 60
#define BHN (BB*NH)   // 24
#define NTICK 768     // 24 heads * 32 tiles
#define NBLK 296      // 148 SMs * 2 blocks

typedef unsigned long long ull;

__device__ __forceinline__ ull fma2(ull a, ull b, ull c){ ull d; asm("fma.rn.f32x2 %0,%1,%2,%3;":"=l"(d):"l"(a),"l"(b),"l"(c)); return d; }
__device__ __forceinline__ ull add2(ull a, ull b){ ull d; asm("add.rn.f32x2 %0,%1,%2;":"=l"(d):"l"(a),"l"(b)); return d; }
__device__ __forceinline__ ull mul2(ull a, ull b){ ull d; asm("mul.rn.f32x2 %0,%1,%2;":"=l"(d):"l"(a),"l"(b)); return d; }
__device__ __forceinline__ ull pack2(float lo, float hi){ ull d; asm("mov.b64 %0,{%1,%2};":"=l"(d):"f"(lo),"f"(hi)); return d; }
__device__ __forceinline__ void unpack2(ull v, float& lo, float& hi){ asm("mov.b64 {%0,%1},%2;":"=f"(lo),"=f"(hi):"l"(v)); }
__device__ __forceinline__ float ex2a(float x){ float y; asm("ex2.approx.f32 %0,%1;":"=f"(y):"f"(x)); return y; }
__device__ __forceinline__ float rcpa(float x){ float y; asm("rcp.approx.f32 %0,%1;":"=f"(y):"f"(x)); return y; }
__device__ __forceinline__ void stcs2(float* p, ull a, ull b){ asm("st.global.cs.v2.b64 [%0],{%1,%2};"::"l"(p),"l"(a),"l"(b):"memory"); }

__device__ __forceinline__ unsigned smem_u32(const void* p){
    unsigned a; asm("{ .reg .u64 t; cvta.to.shared.u64 t, %1; cvt.u32.u64 %0, t; }":"=r"(a):"l"(p)); return a;
}
__device__ __forceinline__ void mbar_init(unsigned m, unsigned cnt){
    asm volatile("mbarrier.init.shared.b64 [%0], %1;"::"r"(m),"r"(cnt):"memory");
}
__device__ __forceinline__ void mbar_expect_tx(unsigned m, unsigned bytes){
    asm volatile("mbarrier.arrive.expect_tx.shared.b64 _, [%0], %1;"::"r"(m),"r"(bytes):"memory");
}
__device__ __forceinline__ void bulk_g2s(unsigned dst, const void* src, unsigned bytes, unsigned m){
    asm volatile("cp.async.bulk.shared::cta.global.mbarrier::complete_tx::bytes [%0], [%1], %2, [%3];"
                 ::"r"(dst),"l"(src),"r"(bytes),"r"(m):"memory");
}
__device__ __forceinline__ void mbar_wait(unsigned m, unsigned parity){
    unsigned done;
    asm volatile("{\n\t.reg .pred p;\n\t"
                 "mbarrier.try_wait.parity.acquire.cta.shared::cta.b64 p, [%1], %2;\n\t"
                 "selp.b32 %0, 1, 0, p;\n\t}"
                 :"=r"(done):"r"(m),"r"(parity):"memory");
    if (!done) {
        asm volatile("{\n\t.reg .pred P1;\n\t"
                     "WL_%=:\n\t"
                     "mbarrier.try_wait.parity.acquire.cta.shared::cta.b64 P1, [%0], %1, 0x989680;\n\t"
                     "@P1 bra.uni WD_%=;\n\t"
                     "bra.uni WL_%=;\n\t"
                     "WD_%=:\n\t}"
                     ::"r"(m),"r"(parity):"memory");
    }
}

// Scratch (device globals; no allocations allowed)
__device__ float g_q[BHN*SQ*DK];
__device__ float g_k[BHN*DK*SQ];
__device__ float g_v[BHN*DK*SQ];
__device__ float g_ctx[BB*SQ*DI];
__device__ int   g_ticket;
__device__ int   g_done[64];     // per (b, 64-row tile) completion counters

// ---------------------------------------------------------------------------
// Kernel 1: QKV projections (R8 base + 4-way acc ILP). Block (0,0) also
// resets the attn ticket + completion counters (proj precedes attn in-stream).
// ---------------------------------------------------------------------------
__global__ __launch_bounds__(512) void proj_kernel(
    const float* __restrict__ Q, const float* __restrict__ K, const float* __restrict__ V,
    const float* __restrict__ Wq, const float* __restrict__ bq,
    const float* __restrict__ Wk, const float* __restrict__ bk,
    const float* __restrict__ Wv, const float* __restrict__ bv)
{
    __shared__ float Ws[DM*DI];
    __shared__ float bs[DI];
    __shared__ float Xs[64][DM];

    int mode = blockIdx.y;
    const float* X; const float* W; const float* bvec;
    if (mode == 0)      { X = Q; W = Wq; bvec = bq; }
    else if (mode == 1) { X = K; W = Wk; bvec = bk; }
    else                { X = V; W = Wv; bvec = bv; }

    int rowbase = blockIdx.x * 64;
    int tid = threadIdx.x;

    if (blockIdx.x == 0 && mode == 0) {
        if (tid < 64) g_done[tid] = 0;
        else if (tid == 64) g_ticket = NBLK;
    }

    for (int idx = tid; idx < DM*DI; idx += 512) Ws[idx] = W[idx];
    for (int idx = tid; idx < 1024; idx += 512)
        ((float4*)Xs)[idx] = ((const float4*)(X + rowbase*DM))[idx];
    if (tid < DI) bs[tid] = bvec[tid];
    __syncthreads();

    int w = tid >> 5, lane = tid & 31;
    int o2  = lane + 32;
    int o2c = (o2 < DI) ? o2 : 0;
    const float SCQ = 0.44721359549995793f * 1.4426950408889634f;

    #pragma unroll
    for (int rr = 0; rr < 4; rr++) {
        int r = w + rr*16;
        float a1a = bs[lane], a1b = 0.f;
        float a2a = bs[o2c],  a2b = 0.f;
        #pragma unroll 8
        for (int m = 0; m < 32; m++) {
            float x0 = Xs[r][m];
            float x1 = Xs[r][m+32];
            a1a = fmaf(x0, Ws[m*DI + lane],      a1a);
            a1b = fmaf(x1, Ws[(m+32)*DI + lane], a1b);
            a2a = fmaf(x0, Ws[m*DI + o2c],       a2a);
            a2b = fmaf(x1, Ws[(m+32)*DI + o2c],  a2b);
        }
        float acc1 = a1a + a1b, acc2 = a2a + a2b;
        int rg = rowbase + r;
        int b = rg >> 11, s = rg & (SQ-1);
        {
            int h = lane / DK, d = lane - h*DK;
            if (mode == 0)      g_q[((b*NH+h)*SQ + s)*DK + d] = acc1 * SCQ;
            else if (mode == 1) g_k[((b*NH+h)*DK + d)*SQ + s] = acc1;
            else                g_v[((b*NH+h)*DK + d)*SQ + s] = acc1;
        }
        if (o2 < DI) {
            int h = o2 / DK, d = o2 - h*DK;
            if (mode == 0)      g_q[((b*NH+h)*SQ + s)*DK + d] = acc2 * SCQ;
            else if (mode == 1) g_k[((b*NH+h)*DK + d)*SQ + s] = acc2;
            else                g_v[((b*NH+h)*DK + d)*SQ + s] = acc2;
        }
    }
}

// ---------------------------------------------------------------------------
// Kernel 2: persistent fused attention + fused output projection.
// 296 blocks x 256 threads, 2/SM. Streaming core identical to R13.
// After a tile's final ctx drain, the 12th block to finish a row-tile
// (all heads) computes out1 = residual + ctx @ Wo + bo for those 64 rows,
// staging Wo in the then-idle `part` smem region.
// ---------------------------------------------------------------------------
#define SM_MBAR  0
#define SM_TICK  6
#define SM_FLAG  7
#define SM_V     8
#define SM_BIAS  (SM_V + 5*SQ)
#define SM_PART  (SM_BIAS + 3*2*SQ)
#define SM_REDB  (SM_PART + 3*10*128)
#define ATTN_SMEM_FLOATS (SM_REDB + 32)
#define ATTN_SMEM_BYTES  (ATTN_SMEM_FLOATS*4)
#define STAGE_BYTES (2*SQ*4)

__global__ __launch_bounds__(256, 2) void attn_kernel(
    const float* __restrict__ bias,
    const float* __restrict__ lam_p,
    float* __restrict__ attn_out,
    const float* __restrict__ Qin,
    const float* __restrict__ Wo,
    const float* __restrict__ bo,
    float* __restrict__ out1)
{
    extern __shared__ float sm[];
    float* Vsm  = sm + SM_V;
    float* bsm  = sm + SM_BIAS;
    float* part = sm + SM_PART;
    float* redb = sm + SM_REDB;
    int*   stick = (int*)(sm + SM_TICK);
    int*   sflag = (int*)(sm + SM_FLAG);
    unsigned mbar0 = smem_u32(sm + SM_MBAR);

    int tid = threadIdx.x, lane = tid & 31, wid = tid >> 5;
    float laml = lam_p[0] * 1.4426950408889634f;
    ull lam2 = pack2(laml, laml);
    int j0 = tid*4, j1 = 1024 + tid*4;

    if (tid == 0) {
        mbar_init(mbar0,      1);
        mbar_init(mbar0 + 8,  1);
        mbar_init(mbar0 + 16, 1);
    }
    __syncthreads();

    int cur = blockIdx.x;
    int P = 0;

    if (tid == 0) {
        int bh0 = cur >> 5, tl0 = cur & 31;
        const float* bb0 = bias + ((size_t)bh0*SQ + tl0*64)*(size_t)SQ;
        #pragma unroll
        for (int s = 0; s < 3; s++) {
            unsigned m = mbar0 + s*8;
            mbar_expect_tx(m, STAGE_BYTES);
            bulk_g2s(smem_u32(bsm + s*2*SQ), bb0 + (size_t)(s*2)*SQ, STAGE_BYTES, m);
        }
    }

    while (cur < NTICK) {
        int bh = cur >> 5, row0 = (cur & 31) * 64;
        int b = bh / NH, hh = bh % NH;
        const float* kg = g_k + (size_t)bh*DK*SQ;
        const float* vg = g_v + (size_t)bh*DK*SQ;
        const float* qg = g_q + ((size_t)bh*SQ + row0)*DK;
        const float* bbase = bias     + ((size_t)bh*SQ + row0)*(size_t)SQ;
        float*       abase = attn_out + ((size_t)bh*SQ + row0)*(size_t)SQ;

        for (int i = tid; i < DK*SQ/4; i += 256)
            ((float4*)Vsm)[i] = ((const float4*)vg)[i];
        ull k2[DK][4];
        #pragma unroll
        for (int d = 0; d < DK; d++) {
            ulonglong2 t = *(const ulonglong2*)(kg + d*SQ + j0);
            k2[d][0] = t.x; k2[d][1] = t.y;
            ulonglong2 u = *(const ulonglong2*)(kg + d*SQ + j1);
            k2[d][2] = u.x; k2[d][3] = u.y;
        }
        if (tid == 0) *stick = atomicAdd(&g_ticket, 1);
        __syncthreads();   // Vsm + ticket visible
        int tick_next = *stick;
        const float* bbase_n = (tick_next < NTICK)
            ? bias + ((size_t)(tick_next >> 5)*SQ + (tick_next & 31)*64)*(size_t)SQ
            : (const float*)0;

        float inv_prev0 = 0.f, inv_prev1 = 0.f;

        for (int lp = 0; lp < 32; lp++, P++) {
            int sl = P % 3;
            mbar_wait(mbar0 + sl*8, (unsigned)((P/3) & 1));

            const float* bst = bsm + sl*2*SQ;
            ull bc[2][4];
            {
                ulonglong2 t0 = *(const ulonglong2*)(bst + j0);
                bc[0][0]=t0.x; bc[0][1]=t0.y;
                ulonglong2 t1 = *(const ulonglong2*)(bst + j1);
                bc[0][2]=t1.x; bc[0][3]=t1.y;
                ulonglong2 t2 = *(const ulonglong2*)(bst + SQ + j0);
                bc[1][0]=t2.x; bc[1][1]=t2.y;
                ulonglong2 t3 = *(const ulonglong2*)(bst + SQ + j1);
                bc[1][2]=t3.x; bc[1][3]=t3.y;
            }

            const float* qp = qg + lp*2*DK;
            ull q2[2][DK];
            #pragma unroll
            for (int r = 0; r < 2; r++)
                #pragma unroll
                for (int d = 0; d < DK; d++) {
                    float qv = qp[r*DK + d];
                    q2[r][d] = pack2(qv, qv);
                }

            ull e2[2][4], ce2[2][DK], ls2[2] = {0ull, 0ull};
            #pragma unroll
            for (int r = 0; r < 2; r++)
                #pragma unroll
                for (int d = 0; d < DK; d++) ce2[r][d] = 0ull;

            #pragma unroll
            for (int hf = 0; hf < 2; hf++) {
                int j = hf ? j1 : j0;
                #pragma unroll
                for (int r = 0; r < 2; r++) {
                    #pragma unroll
                    for (int c = 0; c < 2; c++) {
                        ull s2 = mul2(lam2, bc[r][hf*2+c]);
                        #pragma unroll
                        for (int d = 0; d < DK; d++) s2 = fma2(q2[r][d], k2[d][hf*2+c], s2);
                        float slo, shi; unpack2(s2, slo, shi);
                        ull e = pack2(ex2a(slo), ex2a(shi));
                        e2[r][hf*2+c] = e;
                        ls2[r] = add2(ls2[r], e);
                    }
                }
                ull vd[DK][2];
                #pragma unroll
                for (int d = 0; d < DK; d++) {
                    ulonglong2 t = *(const ulonglong2*)(Vsm + d*SQ + j);
                    vd[d][0] = t.x; vd[d][1] = t.y;
                }
                #pragma unroll
                for (int r = 0; r < 2; r++)
                    #pragma unroll
                    for (int c = 0; c < 2; c++)
                        #pragma unroll
                        for (int d = 0; d < DK; d++)
                            ce2[r][d] = fma2(e2[r][hf*2+c], vd[d][c], ce2[r][d]);
            }

            float ls0, ls1;
            { float a, bq_; unpack2(ls2[0], a, bq_); ls0 = a + bq_;
              unpack2(ls2[1], a, bq_); ls1 = a + bq_; }
            #pragma unroll
            for (int o = 16; o; o >>= 1) {
                ls0 += __shfl_xor_sync(0xffffffffu, ls0, o);
                ls1 += __shfl_xor_sync(0xffffffffu, ls1, o);
            }
            if (lane == 0) ((float2*)redb)[(lp&1)*8 + wid] = make_float2(ls0, ls1);

            #pragma unroll
            for (int r = 0; r < 2; r++)
                #pragma unroll
                for (int d = 0; d < DK; d++) {
                    float a, bq_; unpack2(ce2[r][d], a, bq_);
                    float s = a + bq_;
                    s += __shfl_xor_sync(0xffffffffu, s, 1);
                    if (!(lane & 1)) part[(sl*10 + r*5 + d)*128 + (tid >> 1)] = s;
                }

            __syncthreads();   // the ONLY barrier per pair

            if (tid == 0) {
                int pl = lp + 3;
                const float* src = (const float*)0;
                if (pl < 32)            src = bbase   + (size_t)(pl*2)*SQ;
                else if (bbase_n)       src = bbase_n + (size_t)((pl-32)*2)*SQ;
                if (src) {
                    unsigned m = mbar0 + sl*8;
                    mbar_expect_tx(m, STAGE_BYTES);
                    bulk_g2s(smem_u32(bsm + sl*2*SQ), src, STAGE_BYTES, m);
                }
            }

            float t0 = 0.f, t1 = 0.f;
            {
                const float2* rp = (const float2*)redb + (lp&1)*8;
                #pragma unroll
                for (int w2 = 0; w2 < 8; w2++) { float2 v = rp[w2]; t0 += v.x; t1 += v.y; }
            }
            float inv0 = rcpa(t0), inv1 = rcpa(t1);

            if (lp > 0 && tid < 160) {
                int val = tid >> 4, piece = tid & 15;
                int pprev = (sl == 0) ? 2 : sl - 1;
                const float4* pp = (const float4*)(part + (pprev*10 + val)*128 + piece*8);
                float4 x = pp[0], y = pp[1];
                float s = ((x.x+x.y)+(x.z+x.w)) + ((y.x+y.y)+(y.z+y.w));
                unsigned m = 0xFFFFu << (lane & 16);
                s += __shfl_xor_sync(m, s, 8); s += __shfl_xor_sync(m, s, 4);
                s += __shfl_xor_sync(m, s, 2); s += __shfl_xor_sync(m, s, 1);
                if (piece == 0) {
                    int r = (val >= 5), d = val - r*5;
                    float ip = r ? inv_prev1 : inv_prev0;
                    g_ctx[((size_t)b*SQ + row0 + (lp-1)*2 + r)*DI + hh*DK + d] = s * ip;
                }
            }

            {
                ull i20 = pack2(inv0, inv0), i21 = pack2(inv1, inv1);
                float* a0 = abase + (size_t)(lp*2)*SQ;
                stcs2(a0 + j0,      mul2(e2[0][0], i20), mul2(e2[0][1], i20));
                stcs2(a0 + j1,      mul2(e2[0][2], i20), mul2(e2[0][3], i20));
                stcs2(a0 + SQ + j0, mul2(e2[1][0], i21), mul2(e2[1][1], i21));
                stcs2(a0 + SQ + j1, mul2(e2[1][2], i21), mul2(e2[1][3], i21));
            }
            inv_prev0 = inv0; inv_prev1 = inv1;
        }

        // final drain of this tile's pair 31
        if (tid < 160) {
            int sl31 = (P-1) % 3;
            int val = tid >> 4, piece = tid & 15;
            const float4* pp = (const float4*)(part + (sl31*10 + val)*128 + piece*8);
            float4 x = pp[0], y = pp[1];
            float s = ((x.x+x.y)+(x.z+x.w)) + ((y.x+y.y)+(y.z+y.w));
            unsigned m = 0xFFFFu << (lane & 16);
            s += __shfl_xor_sync(m, s, 8); s += __shfl_xor_sync(m, s, 4);
            s += __shfl_xor_sync(m, s, 2); s += __shfl_xor_sync(m, s, 1);
            if (piece == 0) {
                int r = (val >= 5), d = val - r*5;
                float ip = r ? inv_prev1 : inv_prev0;
                g_ctx[((size_t)b*SQ + row0 + 62 + r)*DI + hh*DK + d] = s * ip;
            }
        }

        // ---- fused output projection: last head of this row-tile does it ----
        __threadfence();   // all threads: publish this tile's g_ctx writes
        __syncthreads();
        if (tid == 0) {
            int rt = (b << 5) + (row0 >> 6);
            int old = atomicAdd(&g_done[rt], 1);
            *sflag = (old == 11);
        }
        __syncthreads();
        if (*sflag) {
            __threadfence();   // acquire side: see other blocks' ctx writes
            // stage Wo [60][64] into part (exactly 3840 floats, idle now)
            for (int i = tid; i < DI*DM/4; i += 256)
                ((float4*)part)[i] = ((const float4*)Wo)[i];
            __syncthreads();
            int row  = tid >> 2;            // 0..63
            int mg   = (tid & 3) * 16;      // column group base
            size_t grow = (size_t)b*SQ + row0 + row;
            const float* cr = g_ctx + grow*DI;
            float acc[16];
            {
                const float4* qr = (const float4*)(Qin + grow*DM + mg);
                const float4* br = (const float4*)(bo + mg);
                #pragma unroll
                for (int kk = 0; kk < 4; kk++) {
                    float4 qv = qr[kk], bv4 = br[kk];
                    acc[kk*4+0] = qv.x + bv4.x; acc[kk*4+1] = qv.y + bv4.y;
                    acc[kk*4+2] = qv.z + bv4.z; acc[kk*4+3] = qv.w + bv4.w;
                }
            }
            #pragma unroll 5
            for (int o = 0; o < DI; o++) {
                float c = cr[o];     // warp-uniform broadcast (same row per 4 lanes)
                const float4* wr = (const float4*)(part + o*DM + mg);
                #pragma unroll
                for (int kk = 0; kk < 4; kk++) {
                    float4 wv = wr[kk];
                    acc[kk*4+0] = fmaf(c, wv.x, acc[kk*4+0]);
                    acc[kk*4+1] = fmaf(c, wv.y, acc[kk*4+1]);
                    acc[kk*4+2] = fmaf(c, wv.z, acc[kk*4+2]);
                    acc[kk*4+3] = fmaf(c, wv.w, acc[kk*4+3]);
                }
            }
            float4* orow = (float4*)(out1 + grow*DM + mg);
            #pragma unroll
            for (int kk = 0; kk < 4; kk++)
                orow[kk] = make_float4(acc[kk*4+0], acc[kk*4+1], acc[kk*4+2], acc[kk*4+3]);
            __syncthreads();   // protect part before next tile's pair-0 writes
        }

        cur = tick_next;
    }
}

// ---------------------------------------------------------------------------
extern "C" void kernel_launch(void* const* d_in, const int* in_sizes, int n_in,
                              void* d_out, int out_size)
{
    const float* Q    = (const float*)d_in[0];
    const float* K    = (const float*)d_in[1];
    const float* V    = (const float*)d_in[2];
    const float* bias = (const float*)d_in[3];
    const float* lam  = (const float*)d_in[4];
    const float* Wq   = (const float*)d_in[5];
    const float* bq   = (const float*)d_in[6];
    const float* Wk   = (const float*)d_in[7];
    const float* bk   = (const float*)d_in[8];
    const float* Wv   = (const float*)d_in[9];
    const float* bv   = (const float*)d_in[10];
    const float* Wo   = (const float*)d_in[11];
    const float* bo   = (const float*)d_in[12];

    float* out1 = (float*)d_out;                 // [B,S,64]
    float* attn = out1 + (size_t)BB*SQ*DM;       // [B,H,S,S]

    cudaFuncSetAttribute(attn_kernel, cudaFuncAttributeMaxDynamicSharedMemorySize,
                         ATTN_SMEM_BYTES);

    proj_kernel<<<dim3(BB*SQ/64, 3), 512>>>(Q, K, V, Wq, bq, Wk, bk, Wv, bv);
    attn_kernel<<<NBLK, 256, ATTN_SMEM_BYTES>>>(bias, lam, attn, Q, Wo, bo, out1);
}

// round 17
// speedup vs baseline: 1.1403x; 1.1403x over previous
#include <cuda_runtime.h>

#define SQ 2048
#define BB 2
#define NH 12
#define DK 5
#define DM 64
#define DI 60
#define BHN (BB*NH)   // 24
#define NTICK 768     // 24 heads * 32 tiles
#define NBLK 296      // 148 SMs * 2 blocks

typedef unsigned long long ull;

__device__ __forceinline__ ull fma2(ull a, ull b, ull c){ ull d; asm("fma.rn.f32x2 %0,%1,%2,%3;":"=l"(d):"l"(a),"l"(b),"l"(c)); return d; }
__device__ __forceinline__ ull add2(ull a, ull b){ ull d; asm("add.rn.f32x2 %0,%1,%2;":"=l"(d):"l"(a),"l"(b)); return d; }
__device__ __forceinline__ ull mul2(ull a, ull b){ ull d; asm("mul.rn.f32x2 %0,%1,%2;":"=l"(d):"l"(a),"l"(b)); return d; }
__device__ __forceinline__ ull pack2(float lo, float hi){ ull d; asm("mov.b64 %0,{%1,%2};":"=l"(d):"f"(lo),"f"(hi)); return d; }
__device__ __forceinline__ void unpack2(ull v, float& lo, float& hi){ asm("mov.b64 {%0,%1},%2;":"=f"(lo),"=f"(hi):"l"(v)); }
__device__ __forceinline__ float ex2a(float x){ float y; asm("ex2.approx.f32 %0,%1;":"=f"(y):"f"(x)); return y; }
__device__ __forceinline__ float rcpa(float x){ float y; asm("rcp.approx.f32 %0,%1;":"=f"(y):"f"(x)); return y; }
__device__ __forceinline__ void stcs2(float* p, ull a, ull b){ asm("st.global.cs.v2.b64 [%0],{%1,%2};"::"l"(p),"l"(a),"l"(b):"memory"); }

__device__ __forceinline__ unsigned smem_u32(const void* p){
    unsigned a; asm("{ .reg .u64 t; cvta.to.shared.u64 t, %1; cvt.u32.u64 %0, t; }":"=r"(a):"l"(p)); return a;
}
__device__ __forceinline__ void mbar_init(unsigned m, unsigned cnt){
    asm volatile("mbarrier.init.shared.b64 [%0], %1;"::"r"(m),"r"(cnt):"memory");
}
__device__ __forceinline__ void mbar_expect_tx(unsigned m, unsigned bytes){
    asm volatile("mbarrier.arrive.expect_tx.shared.b64 _, [%0], %1;"::"r"(m),"r"(bytes):"memory");
}
__device__ __forceinline__ void bulk_g2s(unsigned dst, const void* src, unsigned bytes, unsigned m){
    asm volatile("cp.async.bulk.shared::cta.global.mbarrier::complete_tx::bytes [%0], [%1], %2, [%3];"
                 ::"r"(dst),"l"(src),"r"(bytes),"r"(m):"memory");
}
__device__ __forceinline__ void mbar_wait(unsigned m, unsigned parity){
    unsigned done;
    asm volatile("{\n\t.reg .pred p;\n\t"
                 "mbarrier.try_wait.parity.acquire.cta.shared::cta.b64 p, [%1], %2;\n\t"
                 "selp.b32 %0, 1, 0, p;\n\t}"
                 :"=r"(done):"r"(m),"r"(parity):"memory");
    if (!done) {
        asm volatile("{\n\t.reg .pred P1;\n\t"
                     "WL_%=:\n\t"
                     "mbarrier.try_wait.parity.acquire.cta.shared::cta.b64 P1, [%0], %1, 0x989680;\n\t"
                     "@P1 bra.uni WD_%=;\n\t"
                     "bra.uni WL_%=;\n\t"
                     "WD_%=:\n\t}"
                     ::"r"(m),"r"(parity):"memory");
    }
}

// Scratch (device globals; no allocations allowed)
__device__ float g_q[BHN*SQ*DK];
__device__ float g_k[BHN*DK*SQ];
__device__ float g_v[BHN*DK*SQ];
__device__ float g_ctx[BB*SQ*DI];
__device__ int   g_ticket;

// ---------------------------------------------------------------------------
// Kernel 1: QKV projections (4-acc ILP). Block (0,0) resets the attn ticket.
// ---------------------------------------------------------------------------
__global__ __launch_bounds__(512) void proj_kernel(
    const float* __restrict__ Q, const float* __restrict__ K, const float* __restrict__ V,
    const float* __restrict__ Wq, const float* __restrict__ bq,
    const float* __restrict__ Wk, const float* __restrict__ bk,
    const float* __restrict__ Wv, const float* __restrict__ bv)
{
    __shared__ float Ws[DM*DI];
    __shared__ float bs[DI];
    __shared__ float Xs[64][DM];

    int mode = blockIdx.y;
    const float* X; const float* W; const float* bvec;
    if (mode == 0)      { X = Q; W = Wq; bvec = bq; }
    else if (mode == 1) { X = K; W = Wk; bvec = bk; }
    else                { X = V; W = Wv; bvec = bv; }

    int rowbase = blockIdx.x * 64;
    int tid = threadIdx.x;

    if (blockIdx.x == 0 && mode == 0 && tid == 0) g_ticket = NBLK;

    for (int idx = tid; idx < DM*DI; idx += 512) Ws[idx] = W[idx];
    for (int idx = tid; idx < 1024; idx += 512)
        ((float4*)Xs)[idx] = ((const float4*)(X + rowbase*DM))[idx];
    if (tid < DI) bs[tid] = bvec[tid];
    __syncthreads();

    int w = tid >> 5, lane = tid & 31;
    int o2  = lane + 32;
    int o2c = (o2 < DI) ? o2 : 0;
    const float SCQ = 0.44721359549995793f * 1.4426950408889634f;

    #pragma unroll
    for (int rr = 0; rr < 4; rr++) {
        int r = w + rr*16;
        float a1a = bs[lane], a1b = 0.f;
        float a2a = bs[o2c],  a2b = 0.f;
        #pragma unroll 8
        for (int m = 0; m < 32; m++) {
            float x0 = Xs[r][m];
            float x1 = Xs[r][m+32];
            a1a = fmaf(x0, Ws[m*DI + lane],      a1a);
            a1b = fmaf(x1, Ws[(m+32)*DI + lane], a1b);
            a2a = fmaf(x0, Ws[m*DI + o2c],       a2a);
            a2b = fmaf(x1, Ws[(m+32)*DI + o2c],  a2b);
        }
        float acc1 = a1a + a1b, acc2 = a2a + a2b;
        int rg = rowbase + r;
        int b = rg >> 11, s = rg & (SQ-1);
        {
            int h = lane / DK, d = lane - h*DK;
            if (mode == 0)      g_q[((b*NH+h)*SQ + s)*DK + d] = acc1 * SCQ;
            else if (mode == 1) g_k[((b*NH+h)*DK + d)*SQ + s] = acc1;
            else                g_v[((b*NH+h)*DK + d)*SQ + s] = acc1;
        }
        if (o2 < DI) {
            int h = o2 / DK, d = o2 - h*DK;
            if (mode == 0)      g_q[((b*NH+h)*SQ + s)*DK + d] = acc2 * SCQ;
            else if (mode == 1) g_k[((b*NH+h)*DK + d)*SQ + s] = acc2;
            else                g_v[((b*NH+h)*DK + d)*SQ + s] = acc2;
        }
    }
}

// ---------------------------------------------------------------------------
// Kernel 2: persistent-dynamic fused attention (R13 core, unmodified).
// ---------------------------------------------------------------------------
#define SM_MBAR  0
#define SM_TICK  6
#define SM_V     8
#define SM_BIAS  (SM_V + 5*SQ)
#define SM_PART  (SM_BIAS + 3*2*SQ)
#define SM_REDB  (SM_PART + 3*10*128)
#define ATTN_SMEM_FLOATS (SM_REDB + 32)
#define ATTN_SMEM_BYTES  (ATTN_SMEM_FLOATS*4)
#define STAGE_BYTES (2*SQ*4)

__global__ __launch_bounds__(256, 2) void attn_kernel(
    const float* __restrict__ bias,
    const float* __restrict__ lam_p,
    float* __restrict__ attn_out)
{
    extern __shared__ float sm[];
    float* Vsm  = sm + SM_V;
    float* bsm  = sm + SM_BIAS;
    float* part = sm + SM_PART;
    float* redb = sm + SM_REDB;
    int*   stick = (int*)(sm + SM_TICK);
    unsigned mbar0 = smem_u32(sm + SM_MBAR);

    int tid = threadIdx.x, lane = tid & 31, wid = tid >> 5;
    float laml = lam_p[0] * 1.4426950408889634f;
    ull lam2 = pack2(laml, laml);
    int j0 = tid*4, j1 = 1024 + tid*4;

    if (tid == 0) {
        mbar_init(mbar0,      1);
        mbar_init(mbar0 + 8,  1);
        mbar_init(mbar0 + 16, 1);
    }
    __syncthreads();

    int cur = blockIdx.x;
    int P = 0;

    if (tid == 0) {
        int bh0 = cur >> 5, tl0 = cur & 31;
        const float* bb0 = bias + ((size_t)bh0*SQ + tl0*64)*(size_t)SQ;
        #pragma unroll
        for (int s = 0; s < 3; s++) {
            unsigned m = mbar0 + s*8;
            mbar_expect_tx(m, STAGE_BYTES);
            bulk_g2s(smem_u32(bsm + s*2*SQ), bb0 + (size_t)(s*2)*SQ, STAGE_BYTES, m);
        }
    }

    while (cur < NTICK) {
        int bh = cur >> 5, row0 = (cur & 31) * 64;
        int b = bh / NH, hh = bh % NH;
        const float* kg = g_k + (size_t)bh*DK*SQ;
        const float* vg = g_v + (size_t)bh*DK*SQ;
        const float* qg = g_q + ((size_t)bh*SQ + row0)*DK;
        const float* bbase = bias     + ((size_t)bh*SQ + row0)*(size_t)SQ;
        float*       abase = attn_out + ((size_t)bh*SQ + row0)*(size_t)SQ;

        for (int i = tid; i < DK*SQ/4; i += 256)
            ((float4*)Vsm)[i] = ((const float4*)vg)[i];
        ull k2[DK][4];
        #pragma unroll
        for (int d = 0; d < DK; d++) {
            ulonglong2 t = *(const ulonglong2*)(kg + d*SQ + j0);
            k2[d][0] = t.x; k2[d][1] = t.y;
            ulonglong2 u = *(const ulonglong2*)(kg + d*SQ + j1);
            k2[d][2] = u.x; k2[d][3] = u.y;
        }
        if (tid == 0) *stick = atomicAdd(&g_ticket, 1);
        __syncthreads();   // Vsm + ticket visible
        int tick_next = *stick;
        const float* bbase_n = (tick_next < NTICK)
            ? bias + ((size_t)(tick_next >> 5)*SQ + (tick_next & 31)*64)*(size_t)SQ
            : (const float*)0;

        float inv_prev0 = 0.f, inv_prev1 = 0.f;

        for (int lp = 0; lp < 32; lp++, P++) {
            int sl = P % 3;
            mbar_wait(mbar0 + sl*8, (unsigned)((P/3) & 1));

            const float* bst = bsm + sl*2*SQ;
            ull bc[2][4];
            {
                ulonglong2 t0 = *(const ulonglong2*)(bst + j0);
                bc[0][0]=t0.x; bc[0][1]=t0.y;
                ulonglong2 t1 = *(const ulonglong2*)(bst + j1);
                bc[0][2]=t1.x; bc[0][3]=t1.y;
                ulonglong2 t2 = *(const ulonglong2*)(bst + SQ + j0);
                bc[1][0]=t2.x; bc[1][1]=t2.y;
                ulonglong2 t3 = *(const ulonglong2*)(bst + SQ + j1);
                bc[1][2]=t3.x; bc[1][3]=t3.y;
            }

            const float* qp = qg + lp*2*DK;
            ull q2[2][DK];
            #pragma unroll
            for (int r = 0; r < 2; r++)
                #pragma unroll
                for (int d = 0; d < DK; d++) {
                    float qv = qp[r*DK + d];
                    q2[r][d] = pack2(qv, qv);
                }

            ull e2[2][4], ce2[2][DK], ls2[2] = {0ull, 0ull};
            #pragma unroll
            for (int r = 0; r < 2; r++)
                #pragma unroll
                for (int d = 0; d < DK; d++) ce2[r][d] = 0ull;

            #pragma unroll
            for (int hf = 0; hf < 2; hf++) {
                int j = hf ? j1 : j0;
                #pragma unroll
                for (int r = 0; r < 2; r++) {
                    #pragma unroll
                    for (int c = 0; c < 2; c++) {
                        ull s2 = mul2(lam2, bc[r][hf*2+c]);
                        #pragma unroll
                        for (int d = 0; d < DK; d++) s2 = fma2(q2[r][d], k2[d][hf*2+c], s2);
                        float slo, shi; unpack2(s2, slo, shi);
                        ull e = pack2(ex2a(slo), ex2a(shi));
                        e2[r][hf*2+c] = e;
                        ls2[r] = add2(ls2[r], e);
                    }
                }
                ull vd[DK][2];
                #pragma unroll
                for (int d = 0; d < DK; d++) {
                    ulonglong2 t = *(const ulonglong2*)(Vsm + d*SQ + j);
                    vd[d][0] = t.x; vd[d][1] = t.y;
                }
                #pragma unroll
                for (int r = 0; r < 2; r++)
                    #pragma unroll
                    for (int c = 0; c < 2; c++)
                        #pragma unroll
                        for (int d = 0; d < DK; d++)
                            ce2[r][d] = fma2(e2[r][hf*2+c], vd[d][c], ce2[r][d]);
            }

            float ls0, ls1;
            { float a, bq_; unpack2(ls2[0], a, bq_); ls0 = a + bq_;
              unpack2(ls2[1], a, bq_); ls1 = a + bq_; }
            #pragma unroll
            for (int o = 16; o; o >>= 1) {
                ls0 += __shfl_xor_sync(0xffffffffu, ls0, o);
                ls1 += __shfl_xor_sync(0xffffffffu, ls1, o);
            }
            if (lane == 0) ((float2*)redb)[(lp&1)*8 + wid] = make_float2(ls0, ls1);

            #pragma unroll
            for (int r = 0; r < 2; r++)
                #pragma unroll
                for (int d = 0; d < DK; d++) {
                    float a, bq_; unpack2(ce2[r][d], a, bq_);
                    float s = a + bq_;
                    s += __shfl_xor_sync(0xffffffffu, s, 1);
                    if (!(lane & 1)) part[(sl*10 + r*5 + d)*128 + (tid >> 1)] = s;
                }

            __syncthreads();   // the ONLY barrier per pair

            if (tid == 0) {
                int pl = lp + 3;
                const float* src = (const float*)0;
                if (pl < 32)            src = bbase   + (size_t)(pl*2)*SQ;
                else if (bbase_n)       src = bbase_n + (size_t)((pl-32)*2)*SQ;
                if (src) {
                    unsigned m = mbar0 + sl*8;
                    mbar_expect_tx(m, STAGE_BYTES);
                    bulk_g2s(smem_u32(bsm + sl*2*SQ), src, STAGE_BYTES, m);
                }
            }

            float t0 = 0.f, t1 = 0.f;
            {
                const float2* rp = (const float2*)redb + (lp&1)*8;
                #pragma unroll
                for (int w2 = 0; w2 < 8; w2++) { float2 v = rp[w2]; t0 += v.x; t1 += v.y; }
            }
            float inv0 = rcpa(t0), inv1 = rcpa(t1);

            if (lp > 0 && tid < 160) {
                int val = tid >> 4, piece = tid & 15;
                int pprev = (sl == 0) ? 2 : sl - 1;
                const float4* pp = (const float4*)(part + (pprev*10 + val)*128 + piece*8);
                float4 x = pp[0], y = pp[1];
                float s = ((x.x+x.y)+(x.z+x.w)) + ((y.x+y.y)+(y.z+y.w));
                unsigned m = 0xFFFFu << (lane & 16);
                s += __shfl_xor_sync(m, s, 8); s += __shfl_xor_sync(m, s, 4);
                s += __shfl_xor_sync(m, s, 2); s += __shfl_xor_sync(m, s, 1);
                if (piece == 0) {
                    int r = (val >= 5), d = val - r*5;
                    float ip = r ? inv_prev1 : inv_prev0;
                    g_ctx[((size_t)b*SQ + row0 + (lp-1)*2 + r)*DI + hh*DK + d] = s * ip;
                }
            }

            {
                ull i20 = pack2(inv0, inv0), i21 = pack2(inv1, inv1);
                float* a0 = abase + (size_t)(lp*2)*SQ;
                stcs2(a0 + j0,      mul2(e2[0][0], i20), mul2(e2[0][1], i20));
                stcs2(a0 + j1,      mul2(e2[0][2], i20), mul2(e2[0][3], i20));
                stcs2(a0 + SQ + j0, mul2(e2[1][0], i21), mul2(e2[1][1], i21));
                stcs2(a0 + SQ + j1, mul2(e2[1][2], i21), mul2(e2[1][3], i21));
            }
            inv_prev0 = inv0; inv_prev1 = inv1;
        }

        // final drain of this tile's pair 31
        if (tid < 160) {
            int sl31 = (P-1) % 3;
            int val = tid >> 4, piece = tid & 15;
            const float4* pp = (const float4*)(part + (sl31*10 + val)*128 + piece*8);
            float4 x = pp[0], y = pp[1];
            float s = ((x.x+x.y)+(x.z+x.w)) + ((y.x+y.y)+(y.z+y.w));
            unsigned m = 0xFFFFu << (lane & 16);
            s += __shfl_xor_sync(m, s, 8); s += __shfl_xor_sync(m, s, 4);
            s += __shfl_xor_sync(m, s, 2); s += __shfl_xor_sync(m, s, 1);
            if (piece == 0) {
                int r = (val >= 5), d = val - r*5;
                float ip = r ? inv_prev1 : inv_prev0;
                g_ctx[((size_t)b*SQ + row0 + 62 + r)*DI + hh*DK + d] = s * ip;
            }
        }

        cur = tick_next;
    }
}

// ---------------------------------------------------------------------------
// Kernel 3: out = residual + ctx @ Wo + bo. 16 rows/block. Vectorized fills;
// Qin residual prefetched into registers before the barrier.
// ---------------------------------------------------------------------------
__global__ __launch_bounds__(256) void out_kernel(
    const float* __restrict__ Qin, const float* __restrict__ Wo,
    const float* __restrict__ bo, float* __restrict__ out)
{
    __shared__ float Ws[DI*DM];   // 15.4 KB
    __shared__ float bs[DM];
    __shared__ float Cs[16*DI];   // 3.84 KB
    int tid = threadIdx.x;
    int rowbase = blockIdx.x * 16;

    #pragma unroll
    for (int i = tid; i < DI*DM/4; i += 256)
        ((float4*)Ws)[i] = ((const float4*)Wo)[i];
    if (tid < 16*DI/4) ((float4*)Cs)[tid] = ((const float4*)(g_ctx + rowbase*DI))[tid];
    if (tid < DM) bs[tid] = bo[tid];

    int w = tid >> 5, lane = tid & 31;
    // prefetch residual while smem fills are in flight
    float q1[2], q2v[2];
    #pragma unroll
    for (int rr = 0; rr < 2; rr++) {
        int rg = rowbase + w + rr*8;
        q1[rr]  = Qin[rg*DM + lane];
        q2v[rr] = Qin[rg*DM + lane + 32];
    }
    __syncthreads();

    #pragma unroll
    for (int rr = 0; rr < 2; rr++) {
        int r = w + rr*8;
        int rg = rowbase + r;
        float acc1 = bs[lane]      + q1[rr];
        float acc2 = bs[lane + 32] + q2v[rr];
        #pragma unroll 10
        for (int o = 0; o < DI; o++) {
            float c = Cs[r*DI + o];
            acc1 = fmaf(c, Ws[o*DM + lane],      acc1);
            acc2 = fmaf(c, Ws[o*DM + lane + 32], acc2);
        }
        out[rg*DM + lane]      = acc1;
        out[rg*DM + lane + 32] = acc2;
    }
}

// ---------------------------------------------------------------------------
extern "C" void kernel_launch(void* const* d_in, const int* in_sizes, int n_in,
                              void* d_out, int out_size)
{
    const float* Q    = (const float*)d_in[0];
    const float* K    = (const float*)d_in[1];
    const float* V    = (const float*)d_in[2];
    const float* bias = (const float*)d_in[3];
    const float* lam  = (const float*)d_in[4];
    const float* Wq   = (const float*)d_in[5];
    const float* bq   = (const float*)d_in[6];
    const float* Wk   = (const float*)d_in[7];
    const float* bk   = (const float*)d_in[8];
    const float* Wv   = (const float*)d_in[9];
    const float* bv   = (const float*)d_in[10];
    const float* Wo   = (const float*)d_in[11];
    const float* bo   = (const float*)d_in[12];

    float* out1 = (float*)d_out;                 // [B,S,64]
    float* attn = out1 + (size_t)BB*SQ*DM;       // [B,H,S,S]

    cudaFuncSetAttribute(attn_kernel, cudaFuncAttributeMaxDynamicSharedMemorySize,
                         ATTN_SMEM_BYTES);

    proj_kernel<<<dim3(BB*SQ/64, 3), 512>>>(Q, K, V, Wq, bq, Wk, bk, Wv, bv);
    attn_kernel<<<NBLK, 256, ATTN_SMEM_BYTES>>>(bias, lam, attn);
    out_kernel<<<BB*SQ/16, 256>>>(Q, Wo, bo, out1);
}